// round 1
// baseline (speedup 1.0000x reference)
#include <cuda_runtime.h>
#include <math.h>

// Problem constants (fixed by the reference)
#define BATCH 16
#define CCH   384          // C
#define HN    3136         // H*W = 56*56
#define TC    1152         // 3*C

// ---- scratch (device globals; no allocation allowed) ----
__device__ float g_qkv  [(size_t)BATCH * TC  * HN];   // [b][3C][N]   231 MB
__device__ float g_attn [(size_t)BATCH * CCH * CCH];  // [b][C][C]    9.4 MB
__device__ float g_fused[(size_t)BATCH * CCH * HN];   // [b][C][N]    77 MB
__device__ float g_scale[CCH];
__device__ float g_shift[CCH];

// ---- BN fold: scale = gamma*rsqrt(var+eps), shift = beta - mean*scale ----
__global__ void bn_prep(const float* __restrict__ gamma, const float* __restrict__ beta,
                        const float* __restrict__ mean,  const float* __restrict__ var) {
    int c = threadIdx.x;
    if (c < CCH) {
        float s = gamma[c] * rsqrtf(var[c] + 1e-5f);
        g_scale[c] = s;
        g_shift[c] = beta[c] - mean[c] * s;
    }
}

// ============================================================
// NN SGEMM: C[M,N] = A[M,K](row-major) * B[K,N](row-major)
// optional: per-K-row affine on B (BN fold), per-M bias, residual add.
// Tiles: 64x64x16, 256 threads, 4x4 per-thread micro-tile.
// All dims assumed multiples of (64,64,16) — true for this problem.
// ============================================================
template<bool AFF, bool BIAS, bool RES>
__global__ __launch_bounds__(256)
void sgemm_nn(const float* __restrict__ A, const float* __restrict__ B,
              float* __restrict__ Cout,
              int M, int N, int K,
              long strideA, long strideB, long strideC,
              const float* __restrict__ bias,
              const float* __restrict__ res, long strideRes)
{
    A    += (size_t)blockIdx.z * strideA;
    B    += (size_t)blockIdx.z * strideB;
    Cout += (size_t)blockIdx.z * strideC;
    if (RES) res += (size_t)blockIdx.z * strideRes;

    __shared__ float As[16][68];   // transposed A tile (padded)
    __shared__ float Bs[16][64];

    const int tid = threadIdx.x;
    const int tx = tid & 15, ty = tid >> 4;
    const int row0 = blockIdx.y * 64;
    const int col0 = blockIdx.x * 64;

    const int aRow = tid >> 2,  aCol = (tid & 3) << 2;   // 64 rows x 16 k
    const int bRow = tid >> 4,  bCol = (tid & 15) << 2;  // 16 k   x 64 cols

    float acc[4][4] = {};

    for (int k0 = 0; k0 < K; k0 += 16) {
        float4 av = *(const float4*)&A[(size_t)(row0 + aRow) * K + k0 + aCol];
        As[aCol + 0][aRow] = av.x;
        As[aCol + 1][aRow] = av.y;
        As[aCol + 2][aRow] = av.z;
        As[aCol + 3][aRow] = av.w;

        float4 bv = *(const float4*)&B[(size_t)(k0 + bRow) * N + col0 + bCol];
        if (AFF) {
            float s = g_scale[k0 + bRow], h = g_shift[k0 + bRow];
            bv.x = bv.x * s + h; bv.y = bv.y * s + h;
            bv.z = bv.z * s + h; bv.w = bv.w * s + h;
        }
        *(float4*)&Bs[bRow][bCol] = bv;

        __syncthreads();
        #pragma unroll
        for (int kk = 0; kk < 16; kk++) {
            float4 a = *(const float4*)&As[kk][ty << 2];
            float4 b = *(const float4*)&Bs[kk][tx << 2];
            acc[0][0] += a.x * b.x; acc[0][1] += a.x * b.y; acc[0][2] += a.x * b.z; acc[0][3] += a.x * b.w;
            acc[1][0] += a.y * b.x; acc[1][1] += a.y * b.y; acc[1][2] += a.y * b.z; acc[1][3] += a.y * b.w;
            acc[2][0] += a.z * b.x; acc[2][1] += a.z * b.y; acc[2][2] += a.z * b.z; acc[2][3] += a.z * b.w;
            acc[3][0] += a.w * b.x; acc[3][1] += a.w * b.y; acc[3][2] += a.w * b.z; acc[3][3] += a.w * b.w;
        }
        __syncthreads();
    }

    #pragma unroll
    for (int i = 0; i < 4; i++) {
        int r = row0 + (ty << 2) + i;
        float bi = BIAS ? bias[r] : 0.0f;
        size_t base = (size_t)r * N + col0 + (tx << 2);
        float4 o;
        o.x = acc[i][0] + bi; o.y = acc[i][1] + bi;
        o.z = acc[i][2] + bi; o.w = acc[i][3] + bi;
        if (RES) {
            float4 rv = *(const float4*)&res[base];
            o.x += rv.x; o.y += rv.y; o.z += rv.z; o.w += rv.w;
        }
        *(float4*)&Cout[base] = o;
    }
}

// ============================================================
// NT SGEMM: C[M,N] = A[M,K] * B[N,K]^T  (both K-contiguous)
// ============================================================
__global__ __launch_bounds__(256)
void sgemm_nt(const float* __restrict__ A, const float* __restrict__ B,
              float* __restrict__ Cout,
              int M, int N, int K,
              long strideA, long strideB, long strideC)
{
    A    += (size_t)blockIdx.z * strideA;
    B    += (size_t)blockIdx.z * strideB;
    Cout += (size_t)blockIdx.z * strideC;

    __shared__ float As[16][68];
    __shared__ float Bs[16][68];

    const int tid = threadIdx.x;
    const int tx = tid & 15, ty = tid >> 4;
    const int row0 = blockIdx.y * 64;
    const int col0 = blockIdx.x * 64;

    const int lRow = tid >> 2, lCol = (tid & 3) << 2;  // 64 rows x 16 k each tile

    float acc[4][4] = {};

    for (int k0 = 0; k0 < K; k0 += 16) {
        float4 av = *(const float4*)&A[(size_t)(row0 + lRow) * K + k0 + lCol];
        As[lCol + 0][lRow] = av.x;
        As[lCol + 1][lRow] = av.y;
        As[lCol + 2][lRow] = av.z;
        As[lCol + 3][lRow] = av.w;

        float4 bv = *(const float4*)&B[(size_t)(col0 + lRow) * K + k0 + lCol];
        Bs[lCol + 0][lRow] = bv.x;
        Bs[lCol + 1][lRow] = bv.y;
        Bs[lCol + 2][lRow] = bv.z;
        Bs[lCol + 3][lRow] = bv.w;

        __syncthreads();
        #pragma unroll
        for (int kk = 0; kk < 16; kk++) {
            float4 a = *(const float4*)&As[kk][ty << 2];
            float4 b = *(const float4*)&Bs[kk][tx << 2];
            acc[0][0] += a.x * b.x; acc[0][1] += a.x * b.y; acc[0][2] += a.x * b.z; acc[0][3] += a.x * b.w;
            acc[1][0] += a.y * b.x; acc[1][1] += a.y * b.y; acc[1][2] += a.y * b.z; acc[1][3] += a.y * b.w;
            acc[2][0] += a.z * b.x; acc[2][1] += a.z * b.y; acc[2][2] += a.z * b.z; acc[2][3] += a.z * b.w;
            acc[3][0] += a.w * b.x; acc[3][1] += a.w * b.y; acc[3][2] += a.w * b.z; acc[3][3] += a.w * b.w;
        }
        __syncthreads();
    }

    #pragma unroll
    for (int i = 0; i < 4; i++) {
        int r = row0 + (ty << 2) + i;
        size_t base = (size_t)r * N + col0 + (tx << 2);
        float4 o;
        o.x = acc[i][0]; o.y = acc[i][1]; o.z = acc[i][2]; o.w = acc[i][3];
        *(float4*)&Cout[base] = o;
    }
}

// ---- L2 normalize rows 0..2C-1 of each batch's qkv (q and k), length HN ----
__global__ __launch_bounds__(256)
void l2norm_rows()
{
    const int b = blockIdx.y;
    const int c = blockIdx.x;                  // 0..2C-1
    float* row = g_qkv + ((size_t)b * TC + c) * HN;

    __shared__ float red[256];
    const int tid = threadIdx.x;
    float ss = 0.0f;
    for (int i = tid; i < HN; i += 256) {
        float v = row[i];
        ss += v * v;
    }
    red[tid] = ss;
    __syncthreads();
    for (int s = 128; s > 0; s >>= 1) {
        if (tid < s) red[tid] += red[tid + s];
        __syncthreads();
    }
    float inv = 1.0f / fmaxf(sqrtf(red[0]), 1e-12f);
    for (int i = tid; i < HN; i += 256) row[i] *= inv;
}

// ---- softmax over last dim (C=384) of g_attn, with temperature folded in ----
__global__ __launch_bounds__(128)
void softmax_rows(const float* __restrict__ tptr)
{
    float* row = g_attn + ((size_t)blockIdx.y * CCH + blockIdx.x) * CCH;
    const float t = tptr[0];
    const int tid = threadIdx.x;
    __shared__ float red[128];

    float v0 = row[tid]        * t;
    float v1 = row[tid + 128]  * t;
    float v2 = row[tid + 256]  * t;

    float m = fmaxf(v0, fmaxf(v1, v2));
    red[tid] = m;
    __syncthreads();
    for (int s = 64; s > 0; s >>= 1) {
        if (tid < s) red[tid] = fmaxf(red[tid], red[tid + s]);
        __syncthreads();
    }
    m = red[0];
    __syncthreads();

    float e0 = expf(v0 - m), e1 = expf(v1 - m), e2 = expf(v2 - m);
    red[tid] = e0 + e1 + e2;
    __syncthreads();
    for (int s = 64; s > 0; s >>= 1) {
        if (tid < s) red[tid] += red[tid + s];
        __syncthreads();
    }
    float inv = 1.0f / red[0];

    row[tid]       = e0 * inv;
    row[tid + 128] = e1 * inv;
    row[tid + 256] = e2 * inv;
}

extern "C" void kernel_launch(void* const* d_in, const int* in_sizes, int n_in,
                              void* d_out, int out_size)
{
    const float* x      = (const float*)d_in[0];
    const float* w_qkv  = (const float*)d_in[1];
    const float* b_qkv  = (const float*)d_in[2];
    const float* w_proj = (const float*)d_in[3];
    const float* b_proj = (const float*)d_in[4];
    const float* gamma  = (const float*)d_in[5];
    const float* beta   = (const float*)d_in[6];
    const float* mean   = (const float*)d_in[7];
    const float* var    = (const float*)d_in[8];
    const float* temp   = (const float*)d_in[9];
    float* out = (float*)d_out;

    float *qkv, *attn, *fused;
    cudaGetSymbolAddress((void**)&qkv,   g_qkv);
    cudaGetSymbolAddress((void**)&attn,  g_attn);
    cudaGetSymbolAddress((void**)&fused, g_fused);

    const long sQKV   = (long)TC  * HN;
    const long sCHW   = (long)CCH * HN;
    const long sATT   = (long)CCH * CCH;

    // 0) BN fold
    bn_prep<<<1, CCH>>>(gamma, beta, mean, var);

    // 1) qkv = w_qkv @ BN(x) + b_qkv     [1152 x 3136 x K=384] x16
    sgemm_nn<true, true, false><<<dim3(HN/64, TC/64, BATCH), 256>>>(
        w_qkv, x, qkv, TC, HN, CCH,
        0, sCHW, sQKV, b_qkv, nullptr, 0);

    // 2) L2-normalize q and k rows (first 2C rows per batch)
    l2norm_rows<<<dim3(2*CCH, BATCH), 256>>>();

    // 3) logits = q @ k^T                [384 x 384 x K=3136] x16
    sgemm_nt<<<dim3(CCH/64, CCH/64, BATCH), 256>>>(
        qkv, qkv + (size_t)CCH*HN, attn, CCH, CCH, HN,
        sQKV, sQKV, sATT);

    // 4) softmax(logits * t) over last dim
    softmax_rows<<<dim3(CCH, BATCH), 128>>>(temp);

    // 5) fused = attn @ v                [384 x 3136 x K=384] x16
    sgemm_nn<false, false, false><<<dim3(HN/64, CCH/64, BATCH), 256>>>(
        attn, qkv + (size_t)2*CCH*HN, fused, CCH, HN, CCH,
        sATT, sQKV, sCHW, nullptr, nullptr, 0);

    // 6) out = w_proj @ fused + b_proj + x
    sgemm_nn<false, true, true><<<dim3(HN/64, CCH/64, BATCH), 256>>>(
        w_proj, fused, out, CCH, HN, CCH,
        0, sCHW, sCHW, b_proj, x, sCHW);
}

// round 2
// speedup vs baseline: 1.6653x; 1.6653x over previous
#include <cuda_runtime.h>
#include <math.h>

// Problem constants
#define BATCH 16
#define CCH   384
#define HN    3136
#define TC    1152

// scratch
__device__ float g_qkv  [(size_t)BATCH * TC  * HN];
__device__ float g_attn [(size_t)BATCH * CCH * CCH];
__device__ float g_fused[(size_t)BATCH * CCH * HN];
__device__ float g_scale[CCH];
__device__ float g_shift[CCH];

__global__ void bn_prep(const float* __restrict__ gamma, const float* __restrict__ beta,
                        const float* __restrict__ mean,  const float* __restrict__ var) {
    int c = threadIdx.x;
    if (c < CCH) {
        float s = gamma[c] * rsqrtf(var[c] + 1e-5f);
        g_scale[c] = s;
        g_shift[c] = beta[c] - mean[c] * s;
    }
}

__device__ __forceinline__ unsigned f2tf(float f) {
    unsigned u;
    asm("cvt.rna.tf32.f32 %0, %1;" : "=r"(u) : "f"(f));
    return u;
}

__device__ __forceinline__ void mma_tf32(float* d, const unsigned* a, unsigned b0, unsigned b1) {
    asm volatile(
        "mma.sync.aligned.m16n8k8.row.col.f32.tf32.tf32.f32 "
        "{%0,%1,%2,%3}, {%4,%5,%6,%7}, {%8,%9}, {%0,%1,%2,%3};\n"
        : "+f"(d[0]), "+f"(d[1]), "+f"(d[2]), "+f"(d[3])
        : "r"(a[0]), "r"(a[1]), "r"(a[2]), "r"(a[3]), "r"(b0), "r"(b1));
}

// ============================================================
// NN tf32 MMA GEMM: C[M,N] = A[M,K] * B[K,N]  (both row-major)
// Tile 128x64x16, 256 threads = 8 warps (4M x 2N), warp tile 32x32.
// As[m][k] stride 20, Bs[k][n] stride 72 (conflict-free patterns).
// Dims assumed multiples of (128, 64, 16).
// ============================================================
template<bool AFF, bool BIAS, bool RES>
__global__ __launch_bounds__(256)
void mma_nn(const float* __restrict__ A, const float* __restrict__ B,
            float* __restrict__ Cout,
            int M, int N, int K,
            long strideA, long strideB, long strideC,
            const float* __restrict__ bias,
            const float* __restrict__ res, long strideRes)
{
    A    += (size_t)blockIdx.z * strideA;
    B    += (size_t)blockIdx.z * strideB;
    Cout += (size_t)blockIdx.z * strideC;
    if (RES) res += (size_t)blockIdx.z * strideRes;

    __shared__ unsigned As[2][128 * 20];
    __shared__ unsigned Bs[2][16 * 72];

    const int tid  = threadIdx.x;
    const int wid  = tid >> 5, lane = tid & 31;
    const int wm   = wid >> 1, wn = wid & 1;
    const int grp  = lane >> 2, qd = lane & 3;
    const int row0 = blockIdx.y * 128;
    const int col0 = blockIdx.x * 64;

    // loader indices
    const int arow = tid & 127;       // A row within tile
    const int ai   = tid >> 7;        // 0/1 -> k sub-block of 8
    const int bk   = tid >> 4;        // 0..15 (k row of B tile)
    const int bn4  = tid & 15;        // float4 col index

    float acc[2][4][4] = {};

    const float* Ag = A + (size_t)(row0 + arow) * K + ai * 8;
    const float* Bg = B + (size_t)bk * N + col0 + bn4 * 4;

    // prologue: tile 0
    {
        float4 a0 = *(const float4*)(Ag);
        float4 a1 = *(const float4*)(Ag + 4);
        float4 bv = *(const float4*)(Bg);
        if (AFF) {
            float s = g_scale[bk], h = g_shift[bk];
            bv.x = bv.x * s + h; bv.y = bv.y * s + h;
            bv.z = bv.z * s + h; bv.w = bv.w * s + h;
        }
        uint4 ua0 = { f2tf(a0.x), f2tf(a0.y), f2tf(a0.z), f2tf(a0.w) };
        uint4 ua1 = { f2tf(a1.x), f2tf(a1.y), f2tf(a1.z), f2tf(a1.w) };
        uint4 ub  = { f2tf(bv.x), f2tf(bv.y), f2tf(bv.z), f2tf(bv.w) };
        *(uint4*)&As[0][arow * 20 + ai * 8]     = ua0;
        *(uint4*)&As[0][arow * 20 + ai * 8 + 4] = ua1;
        *(uint4*)&Bs[0][bk * 72 + bn4 * 4]      = ub;
    }
    __syncthreads();

    const int T = K >> 4;
    for (int t = 0; t < T; t++) {
        const int cur = t & 1;
        float4 na0, na1, nbv;
        if (t + 1 < T) {
            const int k0 = (t + 1) << 4;
            na0 = *(const float4*)(Ag + k0);
            na1 = *(const float4*)(Ag + k0 + 4);
            nbv = *(const float4*)(Bg + (size_t)k0 * N);
            if (AFF) {
                float s = g_scale[k0 + bk], h = g_shift[k0 + bk];
                nbv.x = nbv.x * s + h; nbv.y = nbv.y * s + h;
                nbv.z = nbv.z * s + h; nbv.w = nbv.w * s + h;
            }
        }

        const unsigned* Ab = As[cur];
        const unsigned* Bb = Bs[cur];
        #pragma unroll
        for (int ks = 0; ks < 2; ks++) {
            const int kb = ks * 8;
            unsigned af[2][4];
            #pragma unroll
            for (int mi = 0; mi < 2; mi++) {
                int r = wm * 32 + mi * 16 + grp;
                af[mi][0] = Ab[(r    ) * 20 + kb + qd];
                af[mi][1] = Ab[(r + 8) * 20 + kb + qd];
                af[mi][2] = Ab[(r    ) * 20 + kb + qd + 4];
                af[mi][3] = Ab[(r + 8) * 20 + kb + qd + 4];
            }
            #pragma unroll
            for (int ni = 0; ni < 4; ni++) {
                int c = wn * 32 + ni * 8 + grp;
                unsigned b0 = Bb[(kb + qd    ) * 72 + c];
                unsigned b1 = Bb[(kb + qd + 4) * 72 + c];
                #pragma unroll
                for (int mi = 0; mi < 2; mi++)
                    mma_tf32(acc[mi][ni], af[mi], b0, b1);
            }
        }

        if (t + 1 < T) {
            const int nxt = cur ^ 1;
            uint4 ua0 = { f2tf(na0.x), f2tf(na0.y), f2tf(na0.z), f2tf(na0.w) };
            uint4 ua1 = { f2tf(na1.x), f2tf(na1.y), f2tf(na1.z), f2tf(na1.w) };
            uint4 ub  = { f2tf(nbv.x), f2tf(nbv.y), f2tf(nbv.z), f2tf(nbv.w) };
            *(uint4*)&As[nxt][arow * 20 + ai * 8]     = ua0;
            *(uint4*)&As[nxt][arow * 20 + ai * 8 + 4] = ua1;
            *(uint4*)&Bs[nxt][bk * 72 + bn4 * 4]      = ub;
        }
        __syncthreads();
    }

    #pragma unroll
    for (int mi = 0; mi < 2; mi++) {
        #pragma unroll
        for (int ni = 0; ni < 4; ni++) {
            int r = row0 + wm * 32 + mi * 16 + grp;
            int c = col0 + wn * 32 + ni * 8 + 2 * qd;
            float2 v0 = { acc[mi][ni][0], acc[mi][ni][1] };
            float2 v1 = { acc[mi][ni][2], acc[mi][ni][3] };
            if (BIAS) {
                float b0 = bias[r];     v0.x += b0; v0.y += b0;
                float b1 = bias[r + 8]; v1.x += b1; v1.y += b1;
            }
            if (RES) {
                float2 r0 = *(const float2*)&res[(size_t)r * N + c];
                float2 r1 = *(const float2*)&res[(size_t)(r + 8) * N + c];
                v0.x += r0.x; v0.y += r0.y;
                v1.x += r1.x; v1.y += r1.y;
            }
            *(float2*)&Cout[(size_t)r * N + c]       = v0;
            *(float2*)&Cout[(size_t)(r + 8) * N + c] = v1;
        }
    }
}

// ============================================================
// NT tf32 MMA GEMM: C[M,N] = A[M,K] * B[N,K]^T (both K-contiguous)
// As[m][k], Bs[n][k], both stride 20.
// ============================================================
__global__ __launch_bounds__(256)
void mma_nt(const float* __restrict__ A, const float* __restrict__ B,
            float* __restrict__ Cout,
            int M, int N, int K,
            long strideA, long strideB, long strideC)
{
    A    += (size_t)blockIdx.z * strideA;
    B    += (size_t)blockIdx.z * strideB;
    Cout += (size_t)blockIdx.z * strideC;

    __shared__ unsigned As[2][128 * 20];
    __shared__ unsigned Bs[2][64 * 20];

    const int tid  = threadIdx.x;
    const int wid  = tid >> 5, lane = tid & 31;
    const int wm   = wid >> 1, wn = wid & 1;
    const int grp  = lane >> 2, qd = lane & 3;
    const int row0 = blockIdx.y * 128;
    const int col0 = blockIdx.x * 64;

    const int arow = tid & 127;
    const int ai   = tid >> 7;
    const int bn   = tid & 63;     // B row (n) within tile
    const int bi   = tid >> 6;     // 0..3 -> k float4 index

    float acc[2][4][4] = {};

    const float* Ag = A + (size_t)(row0 + arow) * K + ai * 8;
    const float* Bg = B + (size_t)(col0 + bn) * K + bi * 4;

    {
        float4 a0 = *(const float4*)(Ag);
        float4 a1 = *(const float4*)(Ag + 4);
        float4 bv = *(const float4*)(Bg);
        uint4 ua0 = { f2tf(a0.x), f2tf(a0.y), f2tf(a0.z), f2tf(a0.w) };
        uint4 ua1 = { f2tf(a1.x), f2tf(a1.y), f2tf(a1.z), f2tf(a1.w) };
        uint4 ub  = { f2tf(bv.x), f2tf(bv.y), f2tf(bv.z), f2tf(bv.w) };
        *(uint4*)&As[0][arow * 20 + ai * 8]     = ua0;
        *(uint4*)&As[0][arow * 20 + ai * 8 + 4] = ua1;
        *(uint4*)&Bs[0][bn * 20 + bi * 4]       = ub;
    }
    __syncthreads();

    const int T = K >> 4;
    for (int t = 0; t < T; t++) {
        const int cur = t & 1;
        float4 na0, na1, nbv;
        if (t + 1 < T) {
            const int k0 = (t + 1) << 4;
            na0 = *(const float4*)(Ag + k0);
            na1 = *(const float4*)(Ag + k0 + 4);
            nbv = *(const float4*)(Bg + k0);
        }

        const unsigned* Ab = As[cur];
        const unsigned* Bb = Bs[cur];
        #pragma unroll
        for (int ks = 0; ks < 2; ks++) {
            const int kb = ks * 8;
            unsigned af[2][4];
            #pragma unroll
            for (int mi = 0; mi < 2; mi++) {
                int r = wm * 32 + mi * 16 + grp;
                af[mi][0] = Ab[(r    ) * 20 + kb + qd];
                af[mi][1] = Ab[(r + 8) * 20 + kb + qd];
                af[mi][2] = Ab[(r    ) * 20 + kb + qd + 4];
                af[mi][3] = Ab[(r + 8) * 20 + kb + qd + 4];
            }
            #pragma unroll
            for (int ni = 0; ni < 4; ni++) {
                int c = wn * 32 + ni * 8 + grp;
                unsigned b0 = Bb[c * 20 + kb + qd];
                unsigned b1 = Bb[c * 20 + kb + qd + 4];
                #pragma unroll
                for (int mi = 0; mi < 2; mi++)
                    mma_tf32(acc[mi][ni], af[mi], b0, b1);
            }
        }

        if (t + 1 < T) {
            const int nxt = cur ^ 1;
            uint4 ua0 = { f2tf(na0.x), f2tf(na0.y), f2tf(na0.z), f2tf(na0.w) };
            uint4 ua1 = { f2tf(na1.x), f2tf(na1.y), f2tf(na1.z), f2tf(na1.w) };
            uint4 ub  = { f2tf(nbv.x), f2tf(nbv.y), f2tf(nbv.z), f2tf(nbv.w) };
            *(uint4*)&As[nxt][arow * 20 + ai * 8]     = ua0;
            *(uint4*)&As[nxt][arow * 20 + ai * 8 + 4] = ua1;
            *(uint4*)&Bs[nxt][bn * 20 + bi * 4]       = ub;
        }
        __syncthreads();
    }

    #pragma unroll
    for (int mi = 0; mi < 2; mi++) {
        #pragma unroll
        for (int ni = 0; ni < 4; ni++) {
            int r = row0 + wm * 32 + mi * 16 + grp;
            int c = col0 + wn * 32 + ni * 8 + 2 * qd;
            float2 v0 = { acc[mi][ni][0], acc[mi][ni][1] };
            float2 v1 = { acc[mi][ni][2], acc[mi][ni][3] };
            *(float2*)&Cout[(size_t)r * N + c]       = v0;
            *(float2*)&Cout[(size_t)(r + 8) * N + c] = v1;
        }
    }
}

// ---- L2 normalize q and k rows ----
__global__ __launch_bounds__(256)
void l2norm_rows()
{
    const int b = blockIdx.y;
    const int c = blockIdx.x;
    float* row = g_qkv + ((size_t)b * TC + c) * HN;

    __shared__ float red[256];
    const int tid = threadIdx.x;
    float ss = 0.0f;
    for (int i = tid; i < HN; i += 256) {
        float v = row[i];
        ss += v * v;
    }
    red[tid] = ss;
    __syncthreads();
    for (int s = 128; s > 0; s >>= 1) {
        if (tid < s) red[tid] += red[tid + s];
        __syncthreads();
    }
    float inv = 1.0f / fmaxf(sqrtf(red[0]), 1e-12f);
    for (int i = tid; i < HN; i += 256) row[i] *= inv;
}

// ---- softmax over last dim (C=384), temperature folded in ----
__global__ __launch_bounds__(128)
void softmax_rows(const float* __restrict__ tptr)
{
    float* row = g_attn + ((size_t)blockIdx.y * CCH + blockIdx.x) * CCH;
    const float t = tptr[0];
    const int tid = threadIdx.x;
    __shared__ float red[128];

    float v0 = row[tid]       * t;
    float v1 = row[tid + 128] * t;
    float v2 = row[tid + 256] * t;

    float m = fmaxf(v0, fmaxf(v1, v2));
    red[tid] = m;
    __syncthreads();
    for (int s = 64; s > 0; s >>= 1) {
        if (tid < s) red[tid] = fmaxf(red[tid], red[tid + s]);
        __syncthreads();
    }
    m = red[0];
    __syncthreads();

    float e0 = expf(v0 - m), e1 = expf(v1 - m), e2 = expf(v2 - m);
    red[tid] = e0 + e1 + e2;
    __syncthreads();
    for (int s = 64; s > 0; s >>= 1) {
        if (tid < s) red[tid] += red[tid + s];
        __syncthreads();
    }
    float inv = 1.0f / red[0];

    row[tid]       = e0 * inv;
    row[tid + 128] = e1 * inv;
    row[tid + 256] = e2 * inv;
}

extern "C" void kernel_launch(void* const* d_in, const int* in_sizes, int n_in,
                              void* d_out, int out_size)
{
    const float* x      = (const float*)d_in[0];
    const float* w_qkv  = (const float*)d_in[1];
    const float* b_qkv  = (const float*)d_in[2];
    const float* w_proj = (const float*)d_in[3];
    const float* b_proj = (const float*)d_in[4];
    const float* gamma  = (const float*)d_in[5];
    const float* beta   = (const float*)d_in[6];
    const float* mean   = (const float*)d_in[7];
    const float* var    = (const float*)d_in[8];
    const float* temp   = (const float*)d_in[9];
    float* out = (float*)d_out;

    float *qkv, *attn, *fused;
    cudaGetSymbolAddress((void**)&qkv,   g_qkv);
    cudaGetSymbolAddress((void**)&attn,  g_attn);
    cudaGetSymbolAddress((void**)&fused, g_fused);

    const long sQKV = (long)TC  * HN;
    const long sCHW = (long)CCH * HN;
    const long sATT = (long)CCH * CCH;

    bn_prep<<<1, CCH>>>(gamma, beta, mean, var);

    // 1) qkv = w_qkv @ BN(x) + b_qkv     [1152 x 3136 x 384] x16
    mma_nn<true, true, false><<<dim3(HN/64, TC/128, BATCH), 256>>>(
        w_qkv, x, qkv, TC, HN, CCH,
        0, sCHW, sQKV, b_qkv, nullptr, 0);

    // 2) L2-normalize q and k rows
    l2norm_rows<<<dim3(2*CCH, BATCH), 256>>>();

    // 3) logits = q @ k^T                [384 x 384 x 3136] x16
    mma_nt<<<dim3(CCH/64, CCH/128, BATCH), 256>>>(
        qkv, qkv + (size_t)CCH*HN, attn, CCH, CCH, HN,
        sQKV, sQKV, sATT);

    // 4) softmax
    softmax_rows<<<dim3(CCH, BATCH), 128>>>(temp);

    // 5) fused = attn @ v                [384 x 3136 x 384] x16
    mma_nn<false, false, false><<<dim3(HN/64, CCH/128, BATCH), 256>>>(
        attn, qkv + (size_t)2*CCH*HN, fused, CCH, HN, CCH,
        sATT, sQKV, sCHW, nullptr, nullptr, 0);

    // 6) out = w_proj @ fused + b_proj + x
    mma_nn<false, true, true><<<dim3(HN/64, CCH/128, BATCH), 256>>>(
        w_proj, fused, out, CCH, HN, CCH,
        0, sCHW, sCHW, b_proj, x, sCHW);
}

// round 3
// speedup vs baseline: 3.0031x; 1.8033x over previous
#include <cuda_runtime.h>
#include <cuda_bf16.h>
#include <math.h>

#define BATCH 16
#define CCH   384
#define HN    3136
#define TC    1152

__device__ float g_qkv  [(size_t)BATCH * TC  * HN];
__device__ float g_attn [(size_t)BATCH * CCH * CCH];
__device__ float g_fused[(size_t)BATCH * CCH * HN];
__device__ float g_scale[CCH];
__device__ float g_shift[CCH];

__global__ void bn_prep(const float* __restrict__ gamma, const float* __restrict__ beta,
                        const float* __restrict__ mean,  const float* __restrict__ var) {
    int c = threadIdx.x;
    if (c < CCH) {
        float s = gamma[c] * rsqrtf(var[c] + 1e-5f);
        g_scale[c] = s;
        g_shift[c] = beta[c] - mean[c] * s;
    }
}

__device__ __forceinline__ unsigned pk(float a, float b) {
    __nv_bfloat162 h = __floats2bfloat162_rn(a, b);   // x=a (low), y=b (high)
    return *(unsigned*)&h;
}

__device__ __forceinline__ void mma_bf16(float* d, const unsigned* a, unsigned b0, unsigned b1) {
    asm volatile(
        "mma.sync.aligned.m16n8k16.row.col.f32.bf16.bf16.f32 "
        "{%0,%1,%2,%3}, {%4,%5,%6,%7}, {%8,%9}, {%0,%1,%2,%3};\n"
        : "+f"(d[0]), "+f"(d[1]), "+f"(d[2]), "+f"(d[3])
        : "r"(a[0]), "r"(a[1]), "r"(a[2]), "r"(a[3]), "r"(b0), "r"(b1));
}

#define LDSM4(r0,r1,r2,r3,addr) \
    asm volatile("ldmatrix.sync.aligned.m8n8.x4.shared.b16 {%0,%1,%2,%3}, [%4];" \
        : "=r"(r0),"=r"(r1),"=r"(r2),"=r"(r3) : "r"(addr))
#define LDSM4T(r0,r1,r2,r3,addr) \
    asm volatile("ldmatrix.sync.aligned.m8n8.x4.trans.shared.b16 {%0,%1,%2,%3}, [%4];" \
        : "=r"(r0),"=r"(r1),"=r"(r2),"=r"(r3) : "r"(addr))

// Smem byte sizes (per buffer)
#define A_BUF 8192      // 128 rows x 32 bf16 (64B rows)
#define B_BUF 4096      // NN: 32 k-rows x 64 bf16 (128B rows); NT: 64 n-rows x 32 bf16 (64B rows)

// ============================================================
// NN bf16 GEMM: C[M,N] = A[M,K] * B[K,N] (row-major). Tile 128x64x32.
// 256 thr = 8 warps (4M x 2N), warp tile 32x32.
// ============================================================
template<bool AFF, bool BIAS, bool RES>
__global__ __launch_bounds__(256)
void bgemm_nn(const float* __restrict__ A, const float* __restrict__ B,
              float* __restrict__ Cout,
              int M, int N, int K,
              long strideA, long strideB, long strideC,
              const float* __restrict__ bias,
              const float* __restrict__ res, long strideRes)
{
    A    += (size_t)blockIdx.z * strideA;
    B    += (size_t)blockIdx.z * strideB;
    Cout += (size_t)blockIdx.z * strideC;
    if (RES) res += (size_t)blockIdx.z * strideRes;

    __shared__ __align__(16) unsigned char smem[2*A_BUF + 2*B_BUF];
    const unsigned sbase = (unsigned)__cvta_generic_to_shared(smem);
    const unsigned sA0 = sbase, sB0 = sbase + 2*A_BUF;

    const int tid = threadIdx.x;
    const int wid = tid >> 5, lane = tid & 31;
    const int wm = wid >> 1, wn = wid & 1;
    const int grp = lane >> 2, qd = lane & 3;
    const int row0 = blockIdx.y * 128;
    const int col0 = blockIdx.x * 64;

    // ---- loader indices ----
    const int arow = tid >> 1;             // 0..127
    const int aseg = (tid & 1) * 16;       // k offset of 16 floats
    const int asw  = (arow >> 1) & 3;
    const unsigned aoff0 = arow*64 + ((( (tid&1)*2    ) ^ asw) * 16);
    const unsigned aoff1 = arow*64 + ((( (tid&1)*2 + 1) ^ asw) * 16);

    const int bk  = tid >> 3;              // 0..31
    const int bn8 = tid & 7;               // chunk of 8 cols
    const unsigned boff = bk*128 + ((bn8 ^ (bk & 7)) * 16);

    const float* Ag = A + (size_t)(row0 + arow) * K + aseg;
    const float* Bg = B + (size_t)bk * N + col0 + bn8*8;

    // ---- fragment LDSM addresses (per mi / nip, per ks computed inline) ----
    int arow_l[2], achk[2];
    #pragma unroll
    for (int mi = 0; mi < 2; mi++) {
        arow_l[mi] = wm*32 + mi*16 + (lane & 15);
        achk[mi]   = (lane >> 4);            // + ks*2, then ^ swizzle
    }
    const int bk_l  = lane & 15;             // + ks*16
    const int bchkb = wn*4 + (lane >> 4);    // + nip*2, ^ (k&7)

    float acc[2][4][4] = {};

    // ---- prologue load tile 0 ----
    float fa[16]; float fb[8];
    {
        #pragma unroll
        for (int i = 0; i < 4; i++) *(float4*)&fa[i*4] = *(const float4*)(Ag + i*4);
        *(float4*)&fb[0] = *(const float4*)(Bg);
        *(float4*)&fb[4] = *(const float4*)(Bg + 4);
        if (AFF) {
            float s = g_scale[bk], h = g_shift[bk];
            #pragma unroll
            for (int i = 0; i < 8; i++) fb[i] = fb[i]*s + h;
        }
        uint4 u0 = { pk(fa[0],fa[1]), pk(fa[2],fa[3]), pk(fa[4],fa[5]), pk(fa[6],fa[7]) };
        uint4 u1 = { pk(fa[8],fa[9]), pk(fa[10],fa[11]), pk(fa[12],fa[13]), pk(fa[14],fa[15]) };
        uint4 ub = { pk(fb[0],fb[1]), pk(fb[2],fb[3]), pk(fb[4],fb[5]), pk(fb[6],fb[7]) };
        *(uint4*)(smem + aoff0) = u0;
        *(uint4*)(smem + aoff1) = u1;
        *(uint4*)(smem + 2*A_BUF + boff) = ub;
    }
    __syncthreads();

    const int T = K >> 5;
    for (int t = 0; t < T; t++) {
        const int cur = t & 1;
        if (t + 1 < T) {
            const int k0 = (t + 1) << 5;
            #pragma unroll
            for (int i = 0; i < 4; i++) *(float4*)&fa[i*4] = *(const float4*)(Ag + k0 + i*4);
            *(float4*)&fb[0] = *(const float4*)(Bg + (size_t)k0 * N);
            *(float4*)&fb[4] = *(const float4*)(Bg + (size_t)k0 * N + 4);
            if (AFF) {
                float s = g_scale[k0 + bk], h = g_shift[k0 + bk];
                #pragma unroll
                for (int i = 0; i < 8; i++) fb[i] = fb[i]*s + h;
            }
        }

        const unsigned sA = sA0 + cur*A_BUF;
        const unsigned sB = sB0 + cur*B_BUF;
        #pragma unroll
        for (int ks = 0; ks < 2; ks++) {
            unsigned af[2][4];
            #pragma unroll
            for (int mi = 0; mi < 2; mi++) {
                unsigned addr = sA + arow_l[mi]*64 +
                    (((ks*2 + achk[mi]) ^ ((arow_l[mi] >> 1) & 3)) * 16);
                LDSM4(af[mi][0], af[mi][1], af[mi][2], af[mi][3], addr);
            }
            unsigned bf[2][4];
            #pragma unroll
            for (int nip = 0; nip < 2; nip++) {
                int kl = ks*16 + bk_l;
                unsigned addr = sB + kl*128 + (((bchkb + nip*2) ^ (kl & 7)) * 16);
                LDSM4T(bf[nip][0], bf[nip][1], bf[nip][2], bf[nip][3], addr);
            }
            #pragma unroll
            for (int ni = 0; ni < 4; ni++) {
                unsigned b0 = bf[ni>>1][(ni&1)*2];
                unsigned b1 = bf[ni>>1][(ni&1)*2 + 1];
                #pragma unroll
                for (int mi = 0; mi < 2; mi++)
                    mma_bf16(acc[mi][ni], af[mi], b0, b1);
            }
        }

        if (t + 1 < T) {
            const int nxt = cur ^ 1;
            uint4 u0 = { pk(fa[0],fa[1]), pk(fa[2],fa[3]), pk(fa[4],fa[5]), pk(fa[6],fa[7]) };
            uint4 u1 = { pk(fa[8],fa[9]), pk(fa[10],fa[11]), pk(fa[12],fa[13]), pk(fa[14],fa[15]) };
            uint4 ub = { pk(fb[0],fb[1]), pk(fb[2],fb[3]), pk(fb[4],fb[5]), pk(fb[6],fb[7]) };
            *(uint4*)(smem + nxt*A_BUF + aoff0) = u0;
            *(uint4*)(smem + nxt*A_BUF + aoff1) = u1;
            *(uint4*)(smem + 2*A_BUF + nxt*B_BUF + boff) = ub;
        }
        __syncthreads();
    }

    #pragma unroll
    for (int mi = 0; mi < 2; mi++) {
        #pragma unroll
        for (int ni = 0; ni < 4; ni++) {
            int r = row0 + wm*32 + mi*16 + grp;
            int c = col0 + wn*32 + ni*8 + 2*qd;
            float2 v0 = { acc[mi][ni][0], acc[mi][ni][1] };
            float2 v1 = { acc[mi][ni][2], acc[mi][ni][3] };
            if (BIAS) {
                float b0 = bias[r];     v0.x += b0; v0.y += b0;
                float b1 = bias[r + 8]; v1.x += b1; v1.y += b1;
            }
            if (RES) {
                float2 r0 = *(const float2*)&res[(size_t)r * N + c];
                float2 r1 = *(const float2*)&res[(size_t)(r + 8) * N + c];
                v0.x += r0.x; v0.y += r0.y;
                v1.x += r1.x; v1.y += r1.y;
            }
            *(float2*)&Cout[(size_t)r * N + c]       = v0;
            *(float2*)&Cout[(size_t)(r + 8) * N + c] = v1;
        }
    }
}

// ============================================================
// NT bf16 GEMM: C[M,N] = A[M,K] * B[N,K]^T (both K-contiguous). Tile 128x64x32.
// ============================================================
__global__ __launch_bounds__(256)
void bgemm_nt(const float* __restrict__ A, const float* __restrict__ B,
              float* __restrict__ Cout,
              int M, int N, int K,
              long strideA, long strideB, long strideC)
{
    A    += (size_t)blockIdx.z * strideA;
    B    += (size_t)blockIdx.z * strideB;
    Cout += (size_t)blockIdx.z * strideC;

    __shared__ __align__(16) unsigned char smem[2*A_BUF + 2*B_BUF];
    const unsigned sbase = (unsigned)__cvta_generic_to_shared(smem);
    const unsigned sA0 = sbase, sB0 = sbase + 2*A_BUF;

    const int tid = threadIdx.x;
    const int wid = tid >> 5, lane = tid & 31;
    const int wm = wid >> 1, wn = wid & 1;
    const int grp = lane >> 2, qd = lane & 3;
    const int row0 = blockIdx.y * 128;
    const int col0 = blockIdx.x * 64;

    const int arow = tid >> 1;
    const int aseg = (tid & 1) * 16;
    const int asw  = (arow >> 1) & 3;
    const unsigned aoff0 = arow*64 + ((( (tid&1)*2    ) ^ asw) * 16);
    const unsigned aoff1 = arow*64 + ((( (tid&1)*2 + 1) ^ asw) * 16);

    const int bn   = tid >> 2;           // 0..63
    const int bseg = (tid & 3) * 8;      // k offset of 8 floats
    const unsigned boff = bn*64 + ((((tid&3)) ^ ((bn >> 1) & 3)) * 16);

    const float* Ag = A + (size_t)(row0 + arow) * K + aseg;
    const float* Bg = B + (size_t)(col0 + bn) * K + bseg;

    int arow_l[2];
    #pragma unroll
    for (int mi = 0; mi < 2; mi++) arow_l[mi] = wm*32 + mi*16 + (lane & 15);
    const int achk = lane >> 4;
    // B frag (non-trans): n row + octet
    const int bn_l  = wn*32 + (lane >> 4)*8 + (lane & 7);  // + nip*16
    const int boct  = (lane >> 3) & 1;                     // k octet, + ks*2

    float acc[2][4][4] = {};

    float fa[16]; float fb[8];
    {
        #pragma unroll
        for (int i = 0; i < 4; i++) *(float4*)&fa[i*4] = *(const float4*)(Ag + i*4);
        *(float4*)&fb[0] = *(const float4*)(Bg);
        *(float4*)&fb[4] = *(const float4*)(Bg + 4);
        uint4 u0 = { pk(fa[0],fa[1]), pk(fa[2],fa[3]), pk(fa[4],fa[5]), pk(fa[6],fa[7]) };
        uint4 u1 = { pk(fa[8],fa[9]), pk(fa[10],fa[11]), pk(fa[12],fa[13]), pk(fa[14],fa[15]) };
        uint4 ub = { pk(fb[0],fb[1]), pk(fb[2],fb[3]), pk(fb[4],fb[5]), pk(fb[6],fb[7]) };
        *(uint4*)(smem + aoff0) = u0;
        *(uint4*)(smem + aoff1) = u1;
        *(uint4*)(smem + 2*A_BUF + boff) = ub;
    }
    __syncthreads();

    const int T = K >> 5;
    for (int t = 0; t < T; t++) {
        const int cur = t & 1;
        if (t + 1 < T) {
            const int k0 = (t + 1) << 5;
            #pragma unroll
            for (int i = 0; i < 4; i++) *(float4*)&fa[i*4] = *(const float4*)(Ag + k0 + i*4);
            *(float4*)&fb[0] = *(const float4*)(Bg + k0);
            *(float4*)&fb[4] = *(const float4*)(Bg + k0 + 4);
        }

        const unsigned sA = sA0 + cur*A_BUF;
        const unsigned sB = sB0 + cur*B_BUF;
        #pragma unroll
        for (int ks = 0; ks < 2; ks++) {
            unsigned af[2][4];
            #pragma unroll
            for (int mi = 0; mi < 2; mi++) {
                unsigned addr = sA + arow_l[mi]*64 +
                    (((ks*2 + achk) ^ ((arow_l[mi] >> 1) & 3)) * 16);
                LDSM4(af[mi][0], af[mi][1], af[mi][2], af[mi][3], addr);
            }
            unsigned bf[2][4];
            #pragma unroll
            for (int nip = 0; nip < 2; nip++) {
                int nl = bn_l + nip*16;
                unsigned addr = sB + nl*64 + (((ks*2 + boct) ^ ((nl >> 1) & 3)) * 16);
                LDSM4(bf[nip][0], bf[nip][1], bf[nip][2], bf[nip][3], addr);
            }
            #pragma unroll
            for (int ni = 0; ni < 4; ni++) {
                unsigned b0 = bf[ni>>1][(ni&1)*2];
                unsigned b1 = bf[ni>>1][(ni&1)*2 + 1];
                #pragma unroll
                for (int mi = 0; mi < 2; mi++)
                    mma_bf16(acc[mi][ni], af[mi], b0, b1);
            }
        }

        if (t + 1 < T) {
            const int nxt = cur ^ 1;
            uint4 u0 = { pk(fa[0],fa[1]), pk(fa[2],fa[3]), pk(fa[4],fa[5]), pk(fa[6],fa[7]) };
            uint4 u1 = { pk(fa[8],fa[9]), pk(fa[10],fa[11]), pk(fa[12],fa[13]), pk(fa[14],fa[15]) };
            uint4 ub = { pk(fb[0],fb[1]), pk(fb[2],fb[3]), pk(fb[4],fb[5]), pk(fb[6],fb[7]) };
            *(uint4*)(smem + nxt*A_BUF + aoff0) = u0;
            *(uint4*)(smem + nxt*A_BUF + aoff1) = u1;
            *(uint4*)(smem + 2*A_BUF + nxt*B_BUF + boff) = ub;
        }
        __syncthreads();
    }

    #pragma unroll
    for (int mi = 0; mi < 2; mi++) {
        #pragma unroll
        for (int ni = 0; ni < 4; ni++) {
            int r = row0 + wm*32 + mi*16 + grp;
            int c = col0 + wn*32 + ni*8 + 2*qd;
            *(float2*)&Cout[(size_t)r * N + c]       = make_float2(acc[mi][ni][0], acc[mi][ni][1]);
            *(float2*)&Cout[(size_t)(r + 8) * N + c] = make_float2(acc[mi][ni][2], acc[mi][ni][3]);
        }
    }
}

// ---- L2 normalize q and k rows ----
__global__ __launch_bounds__(256)
void l2norm_rows()
{
    const int b = blockIdx.y;
    const int c = blockIdx.x;
    float* row = g_qkv + ((size_t)b * TC + c) * HN;

    __shared__ float red[256];
    const int tid = threadIdx.x;
    float ss = 0.0f;
    for (int i = tid * 4; i < HN; i += 1024) {
        float4 v = *(const float4*)&row[i];
        ss += v.x*v.x + v.y*v.y + v.z*v.z + v.w*v.w;
    }
    red[tid] = ss;
    __syncthreads();
    for (int s = 128; s > 0; s >>= 1) {
        if (tid < s) red[tid] += red[tid + s];
        __syncthreads();
    }
    float inv = 1.0f / fmaxf(sqrtf(red[0]), 1e-12f);
    for (int i = tid * 4; i < HN; i += 1024) {
        float4 v = *(const float4*)&row[i];
        v.x *= inv; v.y *= inv; v.z *= inv; v.w *= inv;
        *(float4*)&row[i] = v;
    }
}

// ---- softmax over last dim (C=384), temperature folded in ----
__global__ __launch_bounds__(128)
void softmax_rows(const float* __restrict__ tptr)
{
    float* row = g_attn + ((size_t)blockIdx.y * CCH + blockIdx.x) * CCH;
    const float t = tptr[0];
    const int tid = threadIdx.x;
    __shared__ float red[128];

    float v0 = row[tid]       * t;
    float v1 = row[tid + 128] * t;
    float v2 = row[tid + 256] * t;

    float m = fmaxf(v0, fmaxf(v1, v2));
    red[tid] = m;
    __syncthreads();
    for (int s = 64; s > 0; s >>= 1) {
        if (tid < s) red[tid] = fmaxf(red[tid], red[tid + s]);
        __syncthreads();
    }
    m = red[0];
    __syncthreads();

    float e0 = expf(v0 - m), e1 = expf(v1 - m), e2 = expf(v2 - m);
    red[tid] = e0 + e1 + e2;
    __syncthreads();
    for (int s = 64; s > 0; s >>= 1) {
        if (tid < s) red[tid] += red[tid + s];
        __syncthreads();
    }
    float inv = 1.0f / red[0];

    row[tid]       = e0 * inv;
    row[tid + 128] = e1 * inv;
    row[tid + 256] = e2 * inv;
}

extern "C" void kernel_launch(void* const* d_in, const int* in_sizes, int n_in,
                              void* d_out, int out_size)
{
    const float* x      = (const float*)d_in[0];
    const float* w_qkv  = (const float*)d_in[1];
    const float* b_qkv  = (const float*)d_in[2];
    const float* w_proj = (const float*)d_in[3];
    const float* b_proj = (const float*)d_in[4];
    const float* gamma  = (const float*)d_in[5];
    const float* beta   = (const float*)d_in[6];
    const float* mean   = (const float*)d_in[7];
    const float* var    = (const float*)d_in[8];
    const float* temp   = (const float*)d_in[9];
    float* out = (float*)d_out;

    float *qkv, *attn, *fused;
    cudaGetSymbolAddress((void**)&qkv,   g_qkv);
    cudaGetSymbolAddress((void**)&attn,  g_attn);
    cudaGetSymbolAddress((void**)&fused, g_fused);

    const long sQKV = (long)TC  * HN;
    const long sCHW = (long)CCH * HN;
    const long sATT = (long)CCH * CCH;

    bn_prep<<<1, CCH>>>(gamma, beta, mean, var);

    // 1) qkv = w_qkv @ BN(x) + b_qkv     [1152 x 3136 x 384] x16
    bgemm_nn<true, true, false><<<dim3(HN/64, TC/128, BATCH), 256>>>(
        w_qkv, x, qkv, TC, HN, CCH,
        0, sCHW, sQKV, b_qkv, nullptr, 0);

    // 2) L2-normalize q and k rows
    l2norm_rows<<<dim3(2*CCH, BATCH), 256>>>();

    // 3) logits = q @ k^T                [384 x 384 x 3136] x16
    bgemm_nt<<<dim3(CCH/64, CCH/128, BATCH), 256>>>(
        qkv, qkv + (size_t)CCH*HN, attn, CCH, CCH, HN,
        sQKV, sQKV, sATT);

    // 4) softmax
    softmax_rows<<<dim3(CCH, BATCH), 128>>>(temp);

    // 5) fused = attn @ v                [384 x 3136 x 384] x16
    bgemm_nn<false, false, false><<<dim3(HN/64, CCH/128, BATCH), 256>>>(
        attn, qkv + (size_t)2*CCH*HN, fused, CCH, HN, CCH,
        sATT, sQKV, sCHW, nullptr, nullptr, 0);

    // 6) out = w_proj @ fused + b_proj + x
    bgemm_nn<false, true, true><<<dim3(HN/64, CCH/128, BATCH), 256>>>(
        w_proj, fused, out, CCH, HN, CCH,
        0, sCHW, sCHW, b_proj, x, sCHW);
}

// round 5
// speedup vs baseline: 5.7475x; 1.9139x over previous
#include <cuda_runtime.h>
#include <cuda_bf16.h>
#include <math.h>

#define BATCH 16
#define CCH   384
#define HN    3136
#define NPAD  3200          // HN padded to multiple of 128
#define TC    1152

// ---------------- scratch (device globals) ----------------
__device__ __nv_bfloat16 g_xT   [(size_t)BATCH * NPAD * CCH];  // BN(x)^T [b][n][c]
__device__ __nv_bfloat16 g_qkvb [(size_t)BATCH * TC * NPAD];   // qkv bf16 [b][3c][n] ld=NPAD
__device__ __nv_bfloat16 g_vT   [(size_t)BATCH * NPAD * CCH];  // v^T [b][n][d]
__device__ float         g_attn [(size_t)BATCH * CCH * CCH];   // logits fp32
__device__ __nv_bfloat16 g_attnb[(size_t)BATCH * CCH * CCH];   // softmax bf16
__device__ __nv_bfloat16 g_fb   [(size_t)BATCH * CCH * NPAD];  // fused bf16 [c][n]
__device__ __nv_bfloat16 g_fT   [(size_t)BATCH * NPAD * CCH];  // fused^T [n][c]
__device__ __nv_bfloat16 g_wqkv [TC * CCH];
__device__ __nv_bfloat16 g_wproj[CCH * CCH];
__device__ float g_scale[CCH];
__device__ float g_shift[CCH];

// ---------------- helpers ----------------
__device__ __forceinline__ unsigned su32(const void* p) {
    return (unsigned)__cvta_generic_to_shared(p);
}
__device__ __forceinline__ unsigned pk(float a, float b) {
    __nv_bfloat162 h = __floats2bfloat162_rn(a, b);
    return *(unsigned*)&h;
}
__device__ __forceinline__ void mma_bf16(float* d, const unsigned* a, unsigned b0, unsigned b1) {
    asm volatile(
        "mma.sync.aligned.m16n8k16.row.col.f32.bf16.bf16.f32 "
        "{%0,%1,%2,%3}, {%4,%5,%6,%7}, {%8,%9}, {%0,%1,%2,%3};\n"
        : "+f"(d[0]), "+f"(d[1]), "+f"(d[2]), "+f"(d[3])
        : "r"(a[0]), "r"(a[1]), "r"(a[2]), "r"(a[3]), "r"(b0), "r"(b1));
}
#define LDSM4(r0,r1,r2,r3,addr) \
    asm volatile("ldmatrix.sync.aligned.m8n8.x4.shared.b16 {%0,%1,%2,%3}, [%4];" \
        : "=r"(r0),"=r"(r1),"=r"(r2),"=r"(r3) : "r"(addr))
#define CP16(dst, src) \
    asm volatile("cp.async.cg.shared.global [%0], [%1], 16;" :: "r"(dst), "l"(src))
#define CP_COMMIT() asm volatile("cp.async.commit_group;" ::: "memory")
#define CP_WAIT1()  asm volatile("cp.async.wait_group 1;" ::: "memory")

#define STAGE_BYTES 16384   // A 8KB + B 8KB

// ============================================================
// NT bf16 GEMM (mma.sync): D[m,n] = sum_k A[m,k]*B[n,k]
// Block tile 128x128xK32, 3-stage cp.async ring, 256 thr = 8 warps (4M x 2N),
// warp tile 32x64. Smem rows 64B, chunk swizzle c ^= (row>>1)&3.
// ============================================================
template<bool BIAS, bool RES, bool OUTBF, bool GUARDN>
__global__ __launch_bounds__(256, 2)
void bgemm(const __nv_bfloat16* __restrict__ A, const __nv_bfloat16* __restrict__ B,
           void* __restrict__ Cv, const float* __restrict__ bias,
           const float* __restrict__ res,
           int K, int lda, int ldb, int ldc, int nvalid,
           long sA, long sB, long sC, long sR)
{
    __shared__ __align__(16) unsigned char smem[3 * STAGE_BYTES];
    const unsigned sbase = su32(smem);

    const int tid = threadIdx.x;
    const int wid = tid >> 5, lane = tid & 31;
    const int wm = wid >> 1, wn = wid & 1;
    const int grp = lane >> 2, qd = lane & 3;
    const int row0 = blockIdx.y * 128;
    const int col0 = blockIdx.x * 128;
    const int z = blockIdx.z;

    const __nv_bfloat16* Ab = A + (size_t)z * sA + (size_t)row0 * lda;
    const __nv_bfloat16* Bb = B + (size_t)z * sB + (size_t)col0 * ldb;

    // loader geometry: idx -> (row 0..127, chunk 0..3 of 16B within 64B row)
    const int lr = tid >> 2, lc = tid & 3;
    const unsigned loffA = (unsigned)(lr * 64 + ((lc ^ ((lr >> 1) & 3)) * 16));
    const int lr2 = (tid + 256) >> 2, lc2 = tid & 3;
    const unsigned loffA2 = (unsigned)(lr2 * 64 + ((lc2 ^ ((lr2 >> 1) & 3)) * 16));

    const int T = K >> 5;

    // fragment geometry
    int arow_l[2];
    #pragma unroll
    for (int mi = 0; mi < 2; mi++) arow_l[mi] = wm * 32 + mi * 16 + (lane & 15);
    const int achk = lane >> 4;
    const int bn_base = wn * 64 + ((lane >> 4) << 3) + (lane & 7);
    const int boct = (lane >> 3) & 1;

    float acc[2][8][4] = {};

    // ---- stage issuance ----
    auto issue = [&](int s, int k0) {
        const unsigned sa = sbase + s * STAGE_BYTES;
        const unsigned sb = sa + 8192;
        CP16(sa + loffA,  Ab + (size_t)lr  * lda + k0 + lc  * 8);
        CP16(sa + loffA2, Ab + (size_t)lr2 * lda + k0 + lc2 * 8);
        CP16(sb + loffA,  Bb + (size_t)lr  * ldb + k0 + lc  * 8);
        CP16(sb + loffA2, Bb + (size_t)lr2 * ldb + k0 + lc2 * 8);
        CP_COMMIT();
    };

    issue(0, 0);
    issue(1, 32);

    for (int t = 0; t < T; t++) {
        CP_WAIT1();
        __syncthreads();

        if (t + 2 < T) {
            int s = (t + 2) % 3;
            issue(s, (t + 2) << 5);
        } else {
            CP_COMMIT();   // keep group accounting uniform
        }

        const unsigned sa = sbase + (t % 3) * STAGE_BYTES;
        const unsigned sb = sa + 8192;

        #pragma unroll
        for (int ks = 0; ks < 2; ks++) {
            unsigned af[2][4];
            #pragma unroll
            for (int mi = 0; mi < 2; mi++) {
                unsigned addr = sa + arow_l[mi] * 64 +
                    (((ks * 2 + achk) ^ ((arow_l[mi] >> 1) & 3)) * 16);
                LDSM4(af[mi][0], af[mi][1], af[mi][2], af[mi][3], addr);
            }
            unsigned bq[4][4];
            #pragma unroll
            for (int nj = 0; nj < 4; nj++) {
                int nl = bn_base + nj * 16;
                unsigned addr = sb + nl * 64 +
                    (((ks * 2 + boct) ^ ((nl >> 1) & 3)) * 16);
                LDSM4(bq[nj][0], bq[nj][1], bq[nj][2], bq[nj][3], addr);
            }
            #pragma unroll
            for (int nj = 0; nj < 4; nj++) {
                #pragma unroll
                for (int p = 0; p < 2; p++) {
                    unsigned b0 = bq[nj][p * 2], b1 = bq[nj][p * 2 + 1];
                    const int ni = nj * 2 + p;
                    #pragma unroll
                    for (int mi = 0; mi < 2; mi++)
                        mma_bf16(acc[mi][ni], af[mi], b0, b1);
                }
            }
        }
    }

    // ---- epilogue ----
    #pragma unroll
    for (int mi = 0; mi < 2; mi++) {
        const int r0 = row0 + wm * 32 + mi * 16 + grp;
        const int r1 = r0 + 8;
        float bv0 = 0.0f, bv1 = 0.0f;
        if (BIAS) { bv0 = bias[r0]; bv1 = bias[r1]; }
        #pragma unroll
        for (int ni = 0; ni < 8; ni++) {
            const int c = col0 + wn * 64 + ni * 8 + 2 * qd;
            if (GUARDN && c >= nvalid) continue;
            float d0 = acc[mi][ni][0] + bv0, d1 = acc[mi][ni][1] + bv0;
            float d2 = acc[mi][ni][2] + bv1, d3 = acc[mi][ni][3] + bv1;
            if (RES) {
                const float* rp = res + (size_t)z * sR;
                float2 q0 = *(const float2*)&rp[(size_t)r0 * ldc + c];
                float2 q1 = *(const float2*)&rp[(size_t)r1 * ldc + c];
                d0 += q0.x; d1 += q0.y; d2 += q1.x; d3 += q1.y;
            }
            if (OUTBF) {
                __nv_bfloat16* Cb = (__nv_bfloat16*)Cv + (size_t)z * sC;
                *(unsigned*)&Cb[(size_t)r0 * ldc + c] = pk(d0, d1);
                *(unsigned*)&Cb[(size_t)r1 * ldc + c] = pk(d2, d3);
            } else {
                float* Cf = (float*)Cv + (size_t)z * sC;
                *(float2*)&Cf[(size_t)r0 * ldc + c] = make_float2(d0, d1);
                *(float2*)&Cf[(size_t)r1 * ldc + c] = make_float2(d2, d3);
            }
        }
    }
}

// ---------------- prep / elementwise ----------------
__global__ void bn_prep(const float* __restrict__ gamma, const float* __restrict__ beta,
                        const float* __restrict__ mean,  const float* __restrict__ var) {
    int c = threadIdx.x;
    if (c < CCH) {
        float s = gamma[c] * rsqrtf(var[c] + 1e-5f);
        g_scale[c] = s;
        g_shift[c] = beta[c] - mean[c] * s;
    }
}

__global__ void f2b(const float* __restrict__ s, __nv_bfloat16* __restrict__ d, int n) {
    int i = blockIdx.x * 256 + threadIdx.x;
    if (i < n) d[i] = __float2bfloat16(s[i]);
}

// x [b][c][3136] fp32 --BN--> xT [b][n][384] bf16 (rows n<3136 filled)
__global__ void prep_xT(const float* __restrict__ x) {
    __shared__ float tl[32][33];
    const int b = blockIdx.z;
    const int n0 = blockIdx.x * 32, c0 = blockIdx.y * 32;
    const int tx = threadIdx.x, ty = threadIdx.y;
    const float* xb = x + (size_t)b * CCH * HN;
    #pragma unroll
    for (int j = 0; j < 4; j++) {
        int c = c0 + ty + j * 8;
        tl[ty + j * 8][tx] = xb[(size_t)c * HN + n0 + tx] * g_scale[c] + g_shift[c];
    }
    __syncthreads();
    __nv_bfloat16* dst = g_xT + (size_t)b * NPAD * CCH;
    #pragma unroll
    for (int j = 0; j < 4; j++) {
        int n = n0 + ty + j * 8;
        dst[(size_t)n * CCH + c0 + tx] = __float2bfloat16(tl[tx][ty + j * 8]);
    }
}

// bf16 transpose [c][n](ldS) -> [n][c](ldD), n<3136, c<384
__global__ void tr_bf(const __nv_bfloat16* __restrict__ src, __nv_bfloat16* __restrict__ dst,
                      long sSrc, long sDst, int ldS, int ldD) {
    __shared__ unsigned short tl[32][36];
    const int b = blockIdx.z;
    const int n0 = blockIdx.x * 32, c0 = blockIdx.y * 32;
    const int tx = threadIdx.x, ty = threadIdx.y;
    const __nv_bfloat16* sp = src + (size_t)b * sSrc;
    __nv_bfloat16* dp = dst + (size_t)b * sDst;
    #pragma unroll
    for (int j = 0; j < 4; j++) {
        int c = c0 + ty + j * 8;
        tl[ty + j * 8][tx] = *(const unsigned short*)&sp[(size_t)c * ldS + n0 + tx];
    }
    __syncthreads();
    #pragma unroll
    for (int j = 0; j < 4; j++) {
        int n = n0 + ty + j * 8;
        *(unsigned short*)&dp[(size_t)n * ldD + c0 + tx] = tl[tx][ty + j * 8];
    }
}

// L2-normalize q,k rows of qkv (first 2C rows), valid length 3136, ld NPAD
__global__ __launch_bounds__(256)
void l2norm_bf() {
    const int b = blockIdx.y;
    const int r = blockIdx.x;
    __nv_bfloat16* row = g_qkvb + ((size_t)b * TC + r) * NPAD;

    __shared__ float red[256];
    const int tid = threadIdx.x;
    float ss = 0.0f;
    for (int i = tid; i < 392; i += 256) {
        uint4 v = *(const uint4*)(row + i * 8);
        const __nv_bfloat162* h = (const __nv_bfloat162*)&v;
        #pragma unroll
        for (int j = 0; j < 4; j++) {
            float2 f = __bfloat1622float2(h[j]);
            ss += f.x * f.x + f.y * f.y;
        }
    }
    red[tid] = ss;
    __syncthreads();
    for (int s = 128; s > 0; s >>= 1) {
        if (tid < s) red[tid] += red[tid + s];
        __syncthreads();
    }
    float inv = 1.0f / fmaxf(sqrtf(red[0]), 1e-12f);
    for (int i = tid; i < 392; i += 256) {
        uint4 v = *(const uint4*)(row + i * 8);
        __nv_bfloat162* h = (__nv_bfloat162*)&v;
        #pragma unroll
        for (int j = 0; j < 4; j++) {
            float2 f = __bfloat1622float2(h[j]);
            h[j] = __floats2bfloat162_rn(f.x * inv, f.y * inv);
        }
        *(uint4*)(row + i * 8) = v;
    }
}

// softmax over last dim (384) of g_attn -> g_attnb bf16
__global__ __launch_bounds__(128)
void softmax_rows(const float* __restrict__ tptr) {
    const size_t ridx = (size_t)blockIdx.y * CCH + blockIdx.x;
    const float* row = g_attn + ridx * CCH;
    __nv_bfloat16* orow = g_attnb + ridx * CCH;
    const float t = tptr[0];
    const int tid = threadIdx.x;
    __shared__ float red[128];

    float v0 = row[tid]       * t;
    float v1 = row[tid + 128] * t;
    float v2 = row[tid + 256] * t;

    float m = fmaxf(v0, fmaxf(v1, v2));
    red[tid] = m;
    __syncthreads();
    for (int s = 64; s > 0; s >>= 1) {
        if (tid < s) red[tid] = fmaxf(red[tid], red[tid + s]);
        __syncthreads();
    }
    m = red[0];
    __syncthreads();

    float e0 = expf(v0 - m), e1 = expf(v1 - m), e2 = expf(v2 - m);
    red[tid] = e0 + e1 + e2;
    __syncthreads();
    for (int s = 64; s > 0; s >>= 1) {
        if (tid < s) red[tid] += red[tid + s];
        __syncthreads();
    }
    float inv = 1.0f / red[0];

    orow[tid]       = __float2bfloat16(e0 * inv);
    orow[tid + 128] = __float2bfloat16(e1 * inv);
    orow[tid + 256] = __float2bfloat16(e2 * inv);
}

// ---------------- host ----------------
extern "C" void kernel_launch(void* const* d_in, const int* in_sizes, int n_in,
                              void* d_out, int out_size)
{
    const float* x      = (const float*)d_in[0];
    const float* w_qkv  = (const float*)d_in[1];
    const float* b_qkv  = (const float*)d_in[2];
    const float* w_proj = (const float*)d_in[3];
    const float* b_proj = (const float*)d_in[4];
    const float* gamma  = (const float*)d_in[5];
    const float* beta   = (const float*)d_in[6];
    const float* mean   = (const float*)d_in[7];
    const float* var    = (const float*)d_in[8];
    const float* temp   = (const float*)d_in[9];
    float* out = (float*)d_out;

    __nv_bfloat16 *xT, *qkvb, *vT, *attnb, *fb, *fT, *wqkvb, *wprojb;
    float *attn;
    cudaGetSymbolAddress((void**)&xT,     g_xT);
    cudaGetSymbolAddress((void**)&qkvb,   g_qkvb);
    cudaGetSymbolAddress((void**)&vT,     g_vT);
    cudaGetSymbolAddress((void**)&attn,   g_attn);
    cudaGetSymbolAddress((void**)&attnb,  g_attnb);
    cudaGetSymbolAddress((void**)&fb,     g_fb);
    cudaGetSymbolAddress((void**)&fT,     g_fT);
    cudaGetSymbolAddress((void**)&wqkvb,  g_wqkv);
    cudaGetSymbolAddress((void**)&wprojb, g_wproj);

    const long sQKV = (long)TC * NPAD;
    const long sNC  = (long)NPAD * CCH;
    const long sATT = (long)CCH * CCH;
    const long sFB  = (long)CCH * NPAD;
    const long sOUT = (long)CCH * HN;

    // 0) prep
    bn_prep<<<1, CCH>>>(gamma, beta, mean, var);
    f2b<<<(TC*CCH + 255)/256, 256>>>(w_qkv, wqkvb, TC*CCH);
    f2b<<<(CCH*CCH + 255)/256, 256>>>(w_proj, wprojb, CCH*CCH);
    prep_xT<<<dim3(HN/32, CCH/32, BATCH), dim3(32, 8)>>>(x);

    // 1) qkv[o,n] = wqkv[o,:] . xT[n,:] + b_qkv   (M=1152, N=3200, K=384)
    bgemm<true, false, true, false><<<dim3(NPAD/128, TC/128, BATCH), 256>>>(
        wqkvb, xT, qkvb, b_qkv, nullptr,
        CCH, CCH, CCH, NPAD, NPAD, 0, sNC, sQKV, 0);

    // 2) l2norm q,k rows
    l2norm_bf<<<dim3(2*CCH, BATCH), 256>>>();

    // 3) v^T  (v = qkv rows [2C, 3C))
    tr_bf<<<dim3(HN/32, CCH/32, BATCH), dim3(32, 8)>>>(
        qkvb + (size_t)2*CCH*NPAD, vT, sQKV, sNC, NPAD, CCH);

    // 4) logits[c,d] = q[c,:] . k[d,:]  (M=384, N=384, K=3136, ld=3200), fp32
    bgemm<false, false, false, false><<<dim3(CCH/128, CCH/128, BATCH), 256>>>(
        qkvb, qkvb + (size_t)CCH*NPAD, attn, nullptr, nullptr,
        HN, NPAD, NPAD, CCH, CCH, sQKV, sQKV, sATT, 0);

    // 5) softmax -> bf16
    softmax_rows<<<dim3(CCH, BATCH), 128>>>(temp);

    // 6) fused[c,n] = attn[c,:] . vT[n,:]  (M=384, N=3200, K=384), bf16
    bgemm<false, false, true, false><<<dim3(NPAD/128, CCH/128, BATCH), 256>>>(
        attnb, vT, fb, nullptr, nullptr,
        CCH, CCH, CCH, NPAD, NPAD, sATT, sNC, sFB, 0);

    // 7) fused^T
    tr_bf<<<dim3(HN/32, CCH/32, BATCH), dim3(32, 8)>>>(
        fb, fT, sFB, sNC, NPAD, CCH);

    // 8) out[o,n] = wproj[o,:] . fT[n,:] + b_proj + x  (fp32, ld=3136, guarded)
    bgemm<true, true, false, true><<<dim3(NPAD/128, CCH/128, BATCH), 256>>>(
        wprojb, fT, out, b_proj, x,
        CCH, CCH, CCH, HN, HN, 0, sNC, sOUT, sOUT);
}

// round 6
// speedup vs baseline: 6.4904x; 1.1293x over previous
#include <cuda_runtime.h>
#include <cuda_bf16.h>
#include <math.h>

#define BATCH 16
#define CCH   384
#define HN    3136
#define NPAD  3200          // HN padded to multiple of 128
#define TC    1152

// ---------------- scratch (device globals, zero-initialized) ----------------
__device__ __nv_bfloat16 g_xT   [(size_t)BATCH * NPAD * CCH];  // BN(x)^T [b][n][c]
__device__ __nv_bfloat16 g_qkvb [(size_t)BATCH * TC * NPAD];   // qkv bf16 [b][3c][n] ld=NPAD
__device__ float         g_attn [(size_t)BATCH * CCH * CCH];   // scaled logits fp32
__device__ __nv_bfloat16 g_attnb[(size_t)BATCH * CCH * CCH];   // softmax bf16
__device__ __nv_bfloat16 g_fb   [(size_t)BATCH * CCH * NPAD];  // fused bf16 [c][n]
__device__ __nv_bfloat16 g_wqkv [TC * CCH];
__device__ __nv_bfloat16 g_wproj[CCH * CCH];
__device__ float g_inv  [BATCH * 2 * CCH];                     // invq[384], invk[384] per batch
__device__ float g_scale[CCH];
__device__ float g_shift[CCH];

// ---------------- helpers ----------------
__device__ __forceinline__ unsigned su32(const void* p) {
    return (unsigned)__cvta_generic_to_shared(p);
}
__device__ __forceinline__ unsigned pk(float a, float b) {
    __nv_bfloat162 h = __floats2bfloat162_rn(a, b);
    return *(unsigned*)&h;
}
__device__ __forceinline__ void mma_bf16(float* d, const unsigned* a, unsigned b0, unsigned b1) {
    asm volatile(
        "mma.sync.aligned.m16n8k16.row.col.f32.bf16.bf16.f32 "
        "{%0,%1,%2,%3}, {%4,%5,%6,%7}, {%8,%9}, {%0,%1,%2,%3};\n"
        : "+f"(d[0]), "+f"(d[1]), "+f"(d[2]), "+f"(d[3])
        : "r"(a[0]), "r"(a[1]), "r"(a[2]), "r"(a[3]), "r"(b0), "r"(b1));
}
#define LDSM4(r0,r1,r2,r3,addr) \
    asm volatile("ldmatrix.sync.aligned.m8n8.x4.shared.b16 {%0,%1,%2,%3}, [%4];" \
        : "=r"(r0),"=r"(r1),"=r"(r2),"=r"(r3) : "r"(addr))
#define LDSM4T(r0,r1,r2,r3,addr) \
    asm volatile("ldmatrix.sync.aligned.m8n8.x4.trans.shared.b16 {%0,%1,%2,%3}, [%4];" \
        : "=r"(r0),"=r"(r1),"=r"(r2),"=r"(r3) : "r"(addr))
#define CP16(dst, src) \
    asm volatile("cp.async.cg.shared.global [%0], [%1], 16;" :: "r"(dst), "l"(src))
#define CP_COMMIT() asm volatile("cp.async.commit_group;" ::: "memory")
#define CP_WAIT1()  asm volatile("cp.async.wait_group 1;" ::: "memory")

#define STAGE_BYTES 16384   // A 8KB + B 8KB

// ============================================================
// bf16 GEMM (mma.sync), block 128x128xK32, 3-stage cp.async ring,
// 256 thr = 8 warps (4M x 2N), warp tile 32x64.
// TRB=true : D[m,n] = sum_k A[m,k]*B[n,k]   (B K-major, "NT")
// TRB=false: D[m,n] = sum_k A[m,k]*B[k,n]   (B row-major, "NN", ldmatrix.trans)
// NN B stage layout: two 4KB halves of [32k][64n], 128B rows,
// chunk swizzle c ^= (k&7). NT layout: 64B rows, c ^= (row>>1)&3.
// ============================================================
template<bool TRB, bool BIAS, bool RES, bool OUTBF, bool GUARDN, bool NORM>
__global__ __launch_bounds__(256, 2)
void bgemm(const __nv_bfloat16* __restrict__ A, const __nv_bfloat16* __restrict__ B,
           void* __restrict__ Cv, const float* __restrict__ bias,
           const float* __restrict__ res, const float* __restrict__ nrm,
           int K, int lda, int ldb, int ldc, int nvalid,
           long sA, long sB, long sC, long sR)
{
    __shared__ __align__(16) unsigned char smem[3 * STAGE_BYTES];
    const unsigned sbase = su32(smem);

    const int tid = threadIdx.x;
    const int wid = tid >> 5, lane = tid & 31;
    const int wm = wid >> 1, wn = wid & 1;
    const int grp = lane >> 2, qd = lane & 3;
    const int row0 = blockIdx.y * 128;
    const int col0 = blockIdx.x * 128;
    const int z = blockIdx.z;

    const __nv_bfloat16* Ab = A + (size_t)z * sA + (size_t)row0 * lda;
    const __nv_bfloat16* Bb = TRB ? (B + (size_t)z * sB + (size_t)col0 * ldb)
                                  : (B + (size_t)z * sB + col0);

    // ---- A loader geometry (rows of 64B, 4 chunks) ----
    const int lr = tid >> 2, lc = tid & 3;
    const unsigned aoff1 = (unsigned)(lr * 64 + ((lc ^ ((lr >> 1) & 3)) * 16));
    const int lr2 = lr + 64;
    const unsigned aoff2 = (unsigned)(lr2 * 64 + ((lc ^ ((lr2 >> 1) & 3)) * 16));

    // ---- NN B loader geometry (32 k-rows x 16 chunks -> 2 halves) ----
    const int nk1 = tid >> 4, nc1 = tid & 15;
    const unsigned nboff1 = (unsigned)((nc1 >> 3) * 4096 + nk1 * 128 + (((nc1 & 7) ^ (nk1 & 7)) * 16));
    const int nk2 = (tid + 256) >> 4, nc2 = tid & 15;
    const unsigned nboff2 = (unsigned)((nc2 >> 3) * 4096 + nk2 * 128 + (((nc2 & 7) ^ (nk2 & 7)) * 16));

    const int T = K >> 5;

    // ---- fragment geometry ----
    int arow_l[2];
    #pragma unroll
    for (int mi = 0; mi < 2; mi++) arow_l[mi] = wm * 32 + mi * 16 + (lane & 15);
    const int achk = lane >> 4;
    // NT B frag
    const int bn_base = wn * 64 + ((lane >> 4) << 3) + (lane & 7);
    const int boct = (lane >> 3) & 1;
    // NN B frag
    const int nn_kl = lane & 15;
    const int nn_ch = lane >> 4;

    float acc[2][8][4] = {};

    auto issue = [&](int s, int k0) {
        const unsigned sa = sbase + s * STAGE_BYTES;
        const unsigned sb = sa + 8192;
        CP16(sa + aoff1, Ab + (size_t)lr  * lda + k0 + lc * 8);
        CP16(sa + aoff2, Ab + (size_t)lr2 * lda + k0 + lc * 8);
        if (TRB) {
            CP16(sb + aoff1, Bb + (size_t)lr  * ldb + k0 + lc * 8);
            CP16(sb + aoff2, Bb + (size_t)lr2 * ldb + k0 + lc * 8);
        } else {
            CP16(sb + nboff1, Bb + (size_t)(k0 + nk1) * ldb + nc1 * 8);
            CP16(sb + nboff2, Bb + (size_t)(k0 + nk2) * ldb + nc2 * 8);
        }
        CP_COMMIT();
    };

    issue(0, 0);
    issue(1, 32);

    for (int t = 0; t < T; t++) {
        CP_WAIT1();
        __syncthreads();

        if (t + 2 < T) issue((t + 2) % 3, (t + 2) << 5);
        else CP_COMMIT();

        const unsigned sa = sbase + (t % 3) * STAGE_BYTES;
        const unsigned sb = sa + 8192;

        #pragma unroll
        for (int ks = 0; ks < 2; ks++) {
            unsigned af[2][4];
            #pragma unroll
            for (int mi = 0; mi < 2; mi++) {
                unsigned addr = sa + arow_l[mi] * 64 +
                    (((ks * 2 + achk) ^ ((arow_l[mi] >> 1) & 3)) * 16);
                LDSM4(af[mi][0], af[mi][1], af[mi][2], af[mi][3], addr);
            }
            unsigned bq[4][4];
            if (TRB) {
                #pragma unroll
                for (int nj = 0; nj < 4; nj++) {
                    int nl = bn_base + nj * 16;
                    unsigned addr = sb + nl * 64 +
                        (((ks * 2 + boct) ^ ((nl >> 1) & 3)) * 16);
                    LDSM4(bq[nj][0], bq[nj][1], bq[nj][2], bq[nj][3], addr);
                }
            } else {
                const int kl = ks * 16 + nn_kl;
                const unsigned sbh = sb + wn * 4096 + kl * 128;
                #pragma unroll
                for (int nj = 0; nj < 4; nj++) {
                    unsigned addr = sbh + (((nj * 2 + nn_ch) ^ (kl & 7)) * 16);
                    LDSM4T(bq[nj][0], bq[nj][1], bq[nj][2], bq[nj][3], addr);
                }
            }
            #pragma unroll
            for (int nj = 0; nj < 4; nj++) {
                #pragma unroll
                for (int p = 0; p < 2; p++) {
                    unsigned b0 = bq[nj][p * 2], b1 = bq[nj][p * 2 + 1];
                    const int ni = nj * 2 + p;
                    #pragma unroll
                    for (int mi = 0; mi < 2; mi++)
                        mma_bf16(acc[mi][ni], af[mi], b0, b1);
                }
            }
        }
    }

    // ---- epilogue ----
    const float* nq = NORM ? (nrm + (size_t)z * 2 * CCH) : nullptr;
    const float* nk = NORM ? (nq + CCH) : nullptr;
    #pragma unroll
    for (int mi = 0; mi < 2; mi++) {
        const int r0 = row0 + wm * 32 + mi * 16 + grp;
        const int r1 = r0 + 8;
        float bv0 = 0.0f, bv1 = 0.0f;
        if (BIAS) { bv0 = bias[r0]; bv1 = bias[r1]; }
        float sr0 = 1.0f, sr1 = 1.0f;
        if (NORM) { sr0 = nq[r0]; sr1 = nq[r1]; }
        #pragma unroll
        for (int ni = 0; ni < 8; ni++) {
            const int c = col0 + wn * 64 + ni * 8 + 2 * qd;
            if (GUARDN && c >= nvalid) continue;
            float d0 = acc[mi][ni][0], d1 = acc[mi][ni][1];
            float d2 = acc[mi][ni][2], d3 = acc[mi][ni][3];
            if (NORM) {
                float c0 = nk[c], c1 = nk[c + 1];
                d0 *= sr0 * c0; d1 *= sr0 * c1;
                d2 *= sr1 * c0; d3 *= sr1 * c1;
            }
            d0 += bv0; d1 += bv0; d2 += bv1; d3 += bv1;
            if (RES) {
                const float* rp = res + (size_t)z * sR;
                float2 q0 = *(const float2*)&rp[(size_t)r0 * ldc + c];
                float2 q1 = *(const float2*)&rp[(size_t)r1 * ldc + c];
                d0 += q0.x; d1 += q0.y; d2 += q1.x; d3 += q1.y;
            }
            if (OUTBF) {
                __nv_bfloat16* Cb = (__nv_bfloat16*)Cv + (size_t)z * sC;
                *(unsigned*)&Cb[(size_t)r0 * ldc + c] = pk(d0, d1);
                *(unsigned*)&Cb[(size_t)r1 * ldc + c] = pk(d2, d3);
            } else {
                float* Cf = (float*)Cv + (size_t)z * sC;
                *(float2*)&Cf[(size_t)r0 * ldc + c] = make_float2(d0, d1);
                *(float2*)&Cf[(size_t)r1 * ldc + c] = make_float2(d2, d3);
            }
        }
    }
}

// ---------------- prep / elementwise ----------------
__global__ void bn_prep(const float* __restrict__ gamma, const float* __restrict__ beta,
                        const float* __restrict__ mean,  const float* __restrict__ var) {
    int c = threadIdx.x;
    if (c < CCH) {
        float s = gamma[c] * rsqrtf(var[c] + 1e-5f);
        g_scale[c] = s;
        g_shift[c] = beta[c] - mean[c] * s;
    }
}

__global__ void f2b(const float* __restrict__ s, __nv_bfloat16* __restrict__ d, int n) {
    int i = blockIdx.x * 256 + threadIdx.x;
    if (i < n) d[i] = __float2bfloat16(s[i]);
}

// x [b][c][3136] fp32 --BN--> xT [b][n][384] bf16
__global__ void prep_xT(const float* __restrict__ x) {
    __shared__ float tl[32][33];
    const int b = blockIdx.z;
    const int n0 = blockIdx.x * 32, c0 = blockIdx.y * 32;
    const int tx = threadIdx.x, ty = threadIdx.y;
    const float* xb = x + (size_t)b * CCH * HN;
    #pragma unroll
    for (int j = 0; j < 4; j++) {
        int c = c0 + ty + j * 8;
        tl[ty + j * 8][tx] = xb[(size_t)c * HN + n0 + tx] * g_scale[c] + g_shift[c];
    }
    __syncthreads();
    __nv_bfloat16* dst = g_xT + (size_t)b * NPAD * CCH;
    #pragma unroll
    for (int j = 0; j < 4; j++) {
        int n = n0 + ty + j * 8;
        dst[(size_t)n * CCH + c0 + tx] = __float2bfloat16(tl[tx][ty + j * 8]);
    }
}

// inverse L2 norms of q,k rows (read-only): g_inv[b][r] = 1/max(|row|,1e-12)
__global__ __launch_bounds__(256)
void rownorm() {
    const int b = blockIdx.y;
    const int r = blockIdx.x;                 // 0..767
    const __nv_bfloat16* row = g_qkvb + ((size_t)b * TC + r) * NPAD;

    __shared__ float red[256];
    const int tid = threadIdx.x;
    float ss = 0.0f;
    for (int i = tid; i < 392; i += 256) {    // 392*8 = 3136
        uint4 v = *(const uint4*)(row + i * 8);
        const __nv_bfloat162* h = (const __nv_bfloat162*)&v;
        #pragma unroll
        for (int j = 0; j < 4; j++) {
            float2 f = __bfloat1622float2(h[j]);
            ss += f.x * f.x + f.y * f.y;
        }
    }
    red[tid] = ss;
    __syncthreads();
    for (int s = 128; s > 0; s >>= 1) {
        if (tid < s) red[tid] += red[tid + s];
        __syncthreads();
    }
    if (tid == 0)
        g_inv[(size_t)b * 2 * CCH + r] = 1.0f / fmaxf(sqrtf(red[0]), 1e-12f);
}

// softmax over last dim (384) of g_attn -> g_attnb bf16
__global__ __launch_bounds__(128)
void softmax_rows(const float* __restrict__ tptr) {
    const size_t ridx = (size_t)blockIdx.y * CCH + blockIdx.x;
    const float* row = g_attn + ridx * CCH;
    __nv_bfloat16* orow = g_attnb + ridx * CCH;
    const float t = tptr[0];
    const int tid = threadIdx.x;
    __shared__ float red[128];

    float v0 = row[tid]       * t;
    float v1 = row[tid + 128] * t;
    float v2 = row[tid + 256] * t;

    float m = fmaxf(v0, fmaxf(v1, v2));
    red[tid] = m;
    __syncthreads();
    for (int s = 64; s > 0; s >>= 1) {
        if (tid < s) red[tid] = fmaxf(red[tid], red[tid + s]);
        __syncthreads();
    }
    m = red[0];
    __syncthreads();

    float e0 = expf(v0 - m), e1 = expf(v1 - m), e2 = expf(v2 - m);
    red[tid] = e0 + e1 + e2;
    __syncthreads();
    for (int s = 64; s > 0; s >>= 1) {
        if (tid < s) red[tid] += red[tid + s];
        __syncthreads();
    }
    float inv = 1.0f / red[0];

    orow[tid]       = __float2bfloat16(e0 * inv);
    orow[tid + 128] = __float2bfloat16(e1 * inv);
    orow[tid + 256] = __float2bfloat16(e2 * inv);
}

// ---------------- host ----------------
extern "C" void kernel_launch(void* const* d_in, const int* in_sizes, int n_in,
                              void* d_out, int out_size)
{
    const float* x      = (const float*)d_in[0];
    const float* w_qkv  = (const float*)d_in[1];
    const float* b_qkv  = (const float*)d_in[2];
    const float* w_proj = (const float*)d_in[3];
    const float* b_proj = (const float*)d_in[4];
    const float* gamma  = (const float*)d_in[5];
    const float* beta   = (const float*)d_in[6];
    const float* mean   = (const float*)d_in[7];
    const float* var    = (const float*)d_in[8];
    const float* temp   = (const float*)d_in[9];
    float* out = (float*)d_out;

    __nv_bfloat16 *xT, *qkvb, *attnb, *fb, *wqkvb, *wprojb;
    float *attn, *invn;
    cudaGetSymbolAddress((void**)&xT,     g_xT);
    cudaGetSymbolAddress((void**)&qkvb,   g_qkvb);
    cudaGetSymbolAddress((void**)&attn,   g_attn);
    cudaGetSymbolAddress((void**)&attnb,  g_attnb);
    cudaGetSymbolAddress((void**)&fb,     g_fb);
    cudaGetSymbolAddress((void**)&wqkvb,  g_wqkv);
    cudaGetSymbolAddress((void**)&wprojb, g_wproj);
    cudaGetSymbolAddress((void**)&invn,   g_inv);

    const long sQKV = (long)TC * NPAD;
    const long sNC  = (long)NPAD * CCH;
    const long sATT = (long)CCH * CCH;
    const long sFB  = (long)CCH * NPAD;
    const long sOUT = (long)CCH * HN;

    // 0) prep
    bn_prep<<<1, CCH>>>(gamma, beta, mean, var);
    f2b<<<(TC*CCH + 255)/256, 256>>>(w_qkv, wqkvb, TC*CCH);
    f2b<<<(CCH*CCH + 255)/256, 256>>>(w_proj, wprojb, CCH*CCH);
    prep_xT<<<dim3(HN/32, CCH/32, BATCH), dim3(32, 8)>>>(x);

    // 1) qkv[o,n] = wqkv[o,:] . xT[n,:] + b_qkv   (NT; M=1152, N=3200, K=384)
    bgemm<true, true, false, true, false, false><<<dim3(NPAD/128, TC/128, BATCH), 256>>>(
        wqkvb, xT, qkvb, b_qkv, nullptr, nullptr,
        CCH, CCH, CCH, NPAD, NPAD, 0, sNC, sQKV, 0);

    // 2) inverse row norms of q,k
    rownorm<<<dim3(2*CCH, BATCH), 256>>>();

    // 3) logits[c,d] = (q[c,:].k[d,:]) * invq[c]*invk[d]   (NT; K=3136), fp32
    bgemm<true, false, false, false, false, true><<<dim3(CCH/128, CCH/128, BATCH), 256>>>(
        qkvb, qkvb + (size_t)CCH*NPAD, attn, nullptr, nullptr, invn,
        HN, NPAD, NPAD, CCH, CCH, sQKV, sQKV, sATT, 0);

    // 4) softmax -> bf16
    softmax_rows<<<dim3(CCH, BATCH), 128>>>(temp);

    // 5) fused[c,n] = attn[c,:] . v[:,n]   (NN; B = v rows of qkv, ld NPAD), bf16
    bgemm<false, false, false, true, false, false><<<dim3(NPAD/128, CCH/128, BATCH), 256>>>(
        attnb, qkvb + (size_t)2*CCH*NPAD, fb, nullptr, nullptr, nullptr,
        CCH, CCH, NPAD, NPAD, NPAD, sATT, sQKV, sFB, 0);

    // 6) out[o,n] = wproj[o,:] . fused[:,n] + b_proj + x   (NN; fp32, guarded)
    bgemm<false, true, true, false, true, false><<<dim3(NPAD/128, CCH/128, BATCH), 256>>>(
        wprojb, fb, out, b_proj, x, nullptr,
        CCH, CCH, NPAD, HN, HN, 0, sFB, sOUT, sOUT);
}